// round 16
// baseline (speedup 1.0000x reference)
#include <cuda_runtime.h>
#include <cuda_fp16.h>
#include <cstdint>

// ============================================================
// Detect head via mma.sync, fp16 operands / fp32 accum.
// R16: R12 champion base (K-chunk=64, double-buffered dynamic
// smem, cp.async W, split MMA, division-free stores) with an
// overlapped two-buffer prologue (v + scoped u) so both chunk-0
// half-load latencies overlap; u dies before acc goes live.
// ============================================================

#define TPB 256
#define SROW 88

// dynamic smem layout
#define XS0 0            // 64 k-rows x 256B (swizzled fp16) = 16384
#define XS1 16384
#define WS0 32768        // 96 n-rows x 144B = 13824
#define WS1 46592
#define SMEM_BYTES 60416

__device__ __forceinline__ uint32_t smem_u32(const void* p) {
    uint32_t a;
    asm("{ .reg .u64 t; cvta.to.shared.u64 t, %1; cvt.u32.u64 %0, t; }" : "=r"(a) : "l"(p));
    return a;
}

#define LDMX4T(r, addr) \
    asm volatile("ldmatrix.sync.aligned.m8n8.x4.trans.shared.b16 {%0,%1,%2,%3}, [%4];" \
        : "=r"((r)[0]), "=r"((r)[1]), "=r"((r)[2]), "=r"((r)[3]) : "r"(addr))

#define LDMX4(r, addr) \
    asm volatile("ldmatrix.sync.aligned.m8n8.x4.shared.b16 {%0,%1,%2,%3}, [%4];" \
        : "=r"((r)[0]), "=r"((r)[1]), "=r"((r)[2]), "=r"((r)[3]) : "r"(addr))

#define MMA16816(d, a, b0, b1) \
    asm volatile("mma.sync.aligned.m16n8k16.row.col.f32.f16.f16.f32 " \
        "{%0,%1,%2,%3}, {%4,%5,%6,%7}, {%8,%9}, {%0,%1,%2,%3};" \
        : "+f"((d)[0]), "+f"((d)[1]), "+f"((d)[2]), "+f"((d)[3]) \
        : "r"((a)[0]), "r"((a)[1]), "r"((a)[2]), "r"((a)[3]), "r"(b0), "r"(b1))

#define CP_ASYNC16(dst, src) \
    asm volatile("cp.async.ca.shared.global [%0], [%1], 16;" :: "r"(dst), "l"(src))
#define CP_COMMIT() asm volatile("cp.async.commit_group;" ::: "memory")
#define CP_WAIT0()  asm volatile("cp.async.wait_group 0;" ::: "memory")

// 28 chunks of 64 channels: [96 n][64 k] fp16 each (12 KB)
__device__ __align__(16) __half g_Wh[28 * 96 * 64];

__global__ void prep_W(const float* __restrict__ W0, const float* __restrict__ W1,
                       const float* __restrict__ W2)
{
    int idx = blockIdx.x * blockDim.x + threadIdx.x;
    if (idx >= 28 * 96 * 64) return;
    int ch = idx / 6144, rem = idx - ch * 6144;
    int n = rem >> 6, k = rem & 63;
    const float* W; int C, cb;
    if (ch < 4)       { W = W0; C = 256;  cb = ch * 64; }
    else if (ch < 12) { W = W1; C = 512;  cb = (ch - 4) * 64; }
    else              { W = W2; C = 1024; cb = (ch - 12) * 64; }
    float v = (n < 85) ? W[(size_t)n * C + cb + k] : 0.0f;
    g_Wh[idx] = __float2half(v);
}

__device__ __forceinline__ uint32_t h2u(__half2 h) {
    return *reinterpret_cast<uint32_t*>(&h);
}

template <int C, int NHW, int NX, int LEVEL>
__device__ __forceinline__
void run_level(const float* __restrict__ X, const float* __restrict__ bias,
               float* __restrict__ out, int lvlOff, int chBase, int b, int m0,
               char* sm, uint32_t sb)
{
    const int tid = threadIdx.x;
    const int lane = tid & 31, wid = tid >> 5;
    const int wm = wid >> 1, wn = wid & 1;
    constexpr int NCH = C / 64;
    const bool fullTile = (m0 + 128 <= NHW);
    const float* Xb = X + (size_t)b * C * NHW;

    // ---- hoisted addresses ----
    const int k0 = tid >> 5, m4 = tid & 31;
    const uint32_t offX0 = (uint32_t)(k0 * 256 + ((m4 * 8) ^ ((k0 & 7) << 4)));

    uint32_t aoffA[2];
    {
        const int mat = lane >> 3, r = lane & 7;
#pragma unroll
        for (int mf = 0; mf < 2; mf++) {
            int kb = ((mat >> 1) << 3) + r;
            int mb = (wm * 32 + mf * 16 + ((mat & 1) << 3)) * 2;
            aoffA[mf] = (uint32_t)(kb * 256 + (mb ^ (r << 4)));
        }
    }
    uint32_t relB[3];
    {
        const int grp = lane >> 3, rsel = lane & 7;
#pragma unroll
        for (int j = 0; j < 3; j++)
            relB[j] = (uint32_t)((wn * 48 + (j * 2 + (grp >> 1)) * 8 + rsel) * 144
                                 + (grp & 1) * 16);
    }

    // load half (32 k-rows) of a chunk into 4 float4 regs
    auto loadX = [&](int chk, int half, float4 (&vv)[4]) {
        const int rbase = chk * 64 + half * 32 + k0;
        if (fullTile) {
            const float* p = Xb + (size_t)rbase * NHW + m0 + m4 * 4;
#pragma unroll
            for (int it = 0; it < 4; it++)
                vv[it] = *reinterpret_cast<const float4*>(p + (size_t)(8 * it) * NHW);
        } else {
            int lim = NHW - 1 - m0;
#pragma unroll
            for (int it = 0; it < 4; it++) {
                const float* src = Xb + (size_t)(rbase + 8 * it) * NHW + m0;
                vv[it].x = src[min(m4 * 4 + 0, lim)];
                vv[it].y = src[min(m4 * 4 + 1, lim)];
                vv[it].z = src[min(m4 * 4 + 2, lim)];
                vv[it].w = src[min(m4 * 4 + 3, lim)];
            }
        }
    };

    auto convertX = [&](const float4 (&vv)[4], uint32_t xsOff, int half) {
        uint32_t base = xsOff + offX0 + (uint32_t)half * 8192;
#pragma unroll
        for (int it = 0; it < 4; it++) {
            __half2 h0 = __floats2half2_rn(vv[it].x, vv[it].y);
            __half2 h1 = __floats2half2_rn(vv[it].z, vv[it].w);
            *reinterpret_cast<uint2*>(sm + base + it * 2048) = make_uint2(h2u(h0), h2u(h1));
        }
    };

    // W: 96 rows x 128B = 768 x 16B units; thread does units tid, +256, +512
    auto stageW = [&](int chk, uint32_t wsOff) {
        const uint4* wsrc = reinterpret_cast<const uint4*>(
            &g_Wh[(size_t)(chBase + chk) * 6144]);
#pragma unroll
        for (int it = 0; it < 3; it++) {
            uint32_t uu = tid + it * TPB;
            CP_ASYNC16(sb + wsOff + (uu >> 3) * 144 + (uu & 7) * 16, wsrc + uu);
        }
        CP_COMMIT();
    };

    // ---- overlapped prologue: both chunk-0 halves in flight together ----
    float4 v[4];
    {
        float4 u[4];                    // scoped: dies before acc goes live
        loadX(0, 0, v);
        loadX(0, 1, u);                 // latencies overlap
        stageW(0, WS0);
        convertX(v, XS0, 0);
        convertX(u, XS0, 1);
    }
    loadX(1 < NCH ? 1 : 0, 0, v);

    float acc[2][6][4];
#pragma unroll
    for (int mf = 0; mf < 2; mf++)
#pragma unroll
        for (int f = 0; f < 6; f++)
#pragma unroll
            for (int e = 0; e < 4; e++) acc[mf][f][e] = 0.0f;

    auto mmaStep = [&](uint32_t xbase, uint32_t wbase, int ks) {
        uint32_t af[2][4];
        LDMX4T(af[0], xbase + aoffA[0] + ks * 4096);
        LDMX4T(af[1], xbase + aoffA[1] + ks * 4096);
#pragma unroll
        for (int j = 0; j < 3; j++) {
            uint32_t br[4];
            LDMX4(br, wbase + relB[j] + ks * 32);
            MMA16816(acc[0][2 * j + 0], af[0], br[0], br[1]);
            MMA16816(acc[1][2 * j + 0], af[1], br[0], br[1]);
            MMA16816(acc[0][2 * j + 1], af[0], br[2], br[3]);
            MMA16816(acc[1][2 * j + 1], af[1], br[2], br[3]);
        }
    };

    CP_WAIT0();
    __syncthreads();

    for (int chk = 0; chk < NCH; chk++) {
        const uint32_t xbase = sb + ((chk & 1) ? XS1 : XS0);
        const uint32_t wbase = sb + ((chk & 1) ? WS1 : WS0);
        const uint32_t xsNxt = (chk & 1) ? XS0 : XS1;
        const uint32_t wsNxt = (chk & 1) ? WS0 : WS1;
        const bool more = (chk + 1 < NCH);

        if (more) {
            stageW(chk + 1, wsNxt);
            convertX(v, xsNxt, 0);          // halfA of next (loaded last iter)
            loadX(chk + 1, 1, v);           // halfB load; covered by first MMA half
        }

        // ---- MMA first half ----
        mmaStep(xbase, wbase, 0);
        mmaStep(xbase, wbase, 1);

        if (more) {
            convertX(v, xsNxt, 1);          // halfB of next (other buffer, no hazard)
            if (chk + 2 < NCH) loadX(chk + 2, 0, v);   // covered by second MMA half
        }

        // ---- MMA second half ----
        mmaStep(xbase, wbase, 2);
        mmaStep(xbase, wbase, 3);

        CP_WAIT0();
        __syncthreads();
    }

    // ---- bias + sigmoid ----
    const int g = lane >> 2, c0 = lane & 3;
#pragma unroll
    for (int f = 0; f < 6; f++) {
        int nb = wn * 48 + f * 8 + c0 * 2;
        float bv0 = (nb < 85) ? __ldg(&bias[nb]) : 0.0f;
        float bv1 = (nb + 1 < 85) ? __ldg(&bias[nb + 1]) : 0.0f;
#pragma unroll
        for (int mf = 0; mf < 2; mf++)
#pragma unroll
            for (int h = 0; h < 2; h++) {
                float p0 = acc[mf][f][h * 2 + 0] + bv0;
                float p1 = acc[mf][f][h * 2 + 1] + bv1;
                acc[mf][f][h * 2 + 0] = __fdividef(1.0f, 1.0f + __expf(-p0));
                acc[mf][f][h * 2 + 1] = __fdividef(1.0f, 1.0f + __expf(-p1));
            }
    }

    // ---- box decode (channels 0..3 live in wn==0, f==0, c0<2) ----
    if (wn == 0) {
        const float power = (float)(1 << LEVEL);
        const float strd  = (float)(8 << LEVEL);
#pragma unroll
        for (int mf = 0; mf < 2; mf++)
#pragma unroll
            for (int h = 0; h < 2; h++) {
                float s0 = acc[mf][0][h * 2 + 0];
                float s1 = acc[mf][0][h * 2 + 1];
                float q0 = 4.0f * s0 * s0 * power;
                float q1 = 4.0f * s1 * s1 * power;
                float p0 = __shfl_xor_sync(0xffffffffu, q0, 1);
                float p1 = __shfl_xor_sync(0xffffffffu, q1, 1);
                float dx1 = (c0 == 0) ? q0 : p0;
                float dy1 = (c0 == 0) ? q1 : p1;
                float dx2 = (c0 == 0) ? p0 : q0;
                float dy2 = (c0 == 0) ? p1 : q1;
                int pos = m0 + wm * 32 + mf * 16 + h * 8 + g;
                int iy = pos / NX, ix = pos - iy * NX;
                float x1 = ((float)ix + 1.0f - dx1) * strd;
                float y1 = ((float)iy + 1.0f - dy1) * strd;
                float x2 = ((float)ix + dx2) * strd;
                float y2 = ((float)iy + dy2) * strd;
                if (c0 == 0) {
                    acc[mf][0][h * 2 + 0] = 0.5f * (x1 + x2);
                    acc[mf][0][h * 2 + 1] = 0.5f * (y1 + y2);
                } else if (c0 == 1) {
                    acc[mf][0][h * 2 + 0] = x2 - x1;
                    acc[mf][0][h * 2 + 1] = y2 - y1;
                }
            }
    }

    // ---- staged coalesced store: 2 waves of 64 positions ----
    float* S = reinterpret_cast<float*>(sm);
#pragma unroll
    for (int w = 0; w < 2; w++) {
        __syncthreads();
        if ((wm >> 1) == w) {
            int mbase = (wm & 1) * 32;
#pragma unroll
            for (int mf = 0; mf < 2; mf++)
#pragma unroll
                for (int h = 0; h < 2; h++) {
                    int mrow = mbase + mf * 16 + h * 8 + g;
#pragma unroll
                    for (int f = 0; f < 6; f++) {
                        int n = wn * 48 + f * 8 + c0 * 2;
                        if (n + 1 < 85)
                            *reinterpret_cast<float2*>(&S[mrow * SROW + n]) =
                                make_float2(acc[mf][f][h * 2], acc[mf][f][h * 2 + 1]);
                        else if (n < 85)
                            S[mrow * SROW + n] = acc[mf][f][h * 2];
                    }
                }
        }
        __syncthreads();
        // division-free warp-per-row stores: warp wid handles rows wid+8r
        int valid = NHW - (m0 + w * 64);
        valid = valid < 0 ? 0 : (valid > 64 ? 64 : valid);
        float* ob = out + ((size_t)b * 8400 + lvlOff + m0 + w * 64) * 85;
#pragma unroll
        for (int r = 0; r < 8; r++) {
            int p = wid + r * 8;
            if (p < valid) {
                const float* srow = &S[p * SROW];
                float* orow = ob + (size_t)p * 85;
                orow[lane] = srow[lane];
                orow[lane + 32] = srow[lane + 32];
                if (lane < 21) orow[lane + 64] = srow[lane + 64];
            }
        }
    }
}

// grid order: L2 (longest, 16 chunks) first, then L1, then L0
__global__ __launch_bounds__(TPB, 2)
void detect_tc(const float* __restrict__ x0, const float* __restrict__ x1,
               const float* __restrict__ x2,
               const float* __restrict__ b0, const float* __restrict__ b1,
               const float* __restrict__ b2, float* __restrict__ out)
{
    extern __shared__ __align__(1024) char sm[];
    uint32_t sb = smem_u32(sm);
    int bid = blockIdx.x;
    if (bid < 64) {                      // L2: 4 tiles x 16 batch
        int b = bid >> 2, t = bid & 3;
        run_level<1024, 400, 20, 2>(x2, b2, out, 8000, 12, b, t * 128, sm, sb);
    } else if (bid < 272) {              // L1: 13 tiles x 16 batch
        int q = bid - 64;
        int b = q / 13, t = q - b * 13;
        run_level<512, 1600, 40, 1>(x1, b1, out, 6400, 4, b, t * 128, sm, sb);
    } else {                             // L0: 50 tiles x 16 batch
        int q = bid - 272;
        int b = q / 50, t = q - b * 50;
        run_level<256, 6400, 80, 0>(x0, b0, out, 0, 0, b, t * 128, sm, sb);
    }
}

extern "C" void kernel_launch(void* const* d_in, const int* in_sizes, int n_in,
                              void* d_out, int out_size)
{
    const float* x0 = (const float*)d_in[0];
    const float* x1 = (const float*)d_in[1];
    const float* x2 = (const float*)d_in[2];
    const float* W0 = (const float*)d_in[3];
    const float* b0 = (const float*)d_in[4];
    const float* W1 = (const float*)d_in[5];
    const float* b1 = (const float*)d_in[6];
    const float* W2 = (const float*)d_in[7];
    const float* b2 = (const float*)d_in[8];
    float* out = (float*)d_out;

    cudaFuncSetAttribute(detect_tc, cudaFuncAttributeMaxDynamicSharedMemorySize,
                         SMEM_BYTES);
    prep_W<<<(28 * 96 * 64 + 255) / 256, 256>>>(W0, W1, W2);
    detect_tc<<<64 + 208 + 800, TPB, SMEM_BYTES>>>(x0, x1, x2, b0, b1, b2, out);
}

// round 17
// speedup vs baseline: 1.1034x; 1.1034x over previous
#include <cuda_runtime.h>
#include <cuda_fp16.h>
#include <cstdint>

// ============================================================
// Detect head via mma.sync, fp16 operands AND fp16 accumulators
// (fp32 bias/sigmoid/decode in epilogue). Acc = 24 regs ->
// 3 CTAs/SM (24 warps). K-chunk=64, double-buffered dynamic
// smem, cp.async W, split MMA, division-free stores.
// ============================================================

#define TPB 256
#define SROW 88

// dynamic smem layout
#define XS0 0            // 64 k-rows x 256B (swizzled fp16) = 16384
#define XS1 16384
#define WS0 32768        // 96 n-rows x 144B = 13824
#define WS1 46592
#define SMEM_BYTES 60416

__device__ __forceinline__ uint32_t smem_u32(const void* p) {
    uint32_t a;
    asm("{ .reg .u64 t; cvta.to.shared.u64 t, %1; cvt.u32.u64 %0, t; }" : "=r"(a) : "l"(p));
    return a;
}

#define LDMX4T(r, addr) \
    asm volatile("ldmatrix.sync.aligned.m8n8.x4.trans.shared.b16 {%0,%1,%2,%3}, [%4];" \
        : "=r"((r)[0]), "=r"((r)[1]), "=r"((r)[2]), "=r"((r)[3]) : "r"(addr))

#define LDMX4(r, addr) \
    asm volatile("ldmatrix.sync.aligned.m8n8.x4.shared.b16 {%0,%1,%2,%3}, [%4];" \
        : "=r"((r)[0]), "=r"((r)[1]), "=r"((r)[2]), "=r"((r)[3]) : "r"(addr))

// fp16-accumulator MMA: D(2 regs) = A(4) * B(2) + D
#define MMA16816H(d, a, b0, b1) \
    asm volatile("mma.sync.aligned.m16n8k16.row.col.f16.f16.f16.f16 " \
        "{%0,%1}, {%2,%3,%4,%5}, {%6,%7}, {%0,%1};" \
        : "+r"((d)[0]), "+r"((d)[1]) \
        : "r"((a)[0]), "r"((a)[1]), "r"((a)[2]), "r"((a)[3]), "r"(b0), "r"(b1))

#define CP_ASYNC16(dst, src) \
    asm volatile("cp.async.ca.shared.global [%0], [%1], 16;" :: "r"(dst), "l"(src))
#define CP_COMMIT() asm volatile("cp.async.commit_group;" ::: "memory")
#define CP_WAIT0()  asm volatile("cp.async.wait_group 0;" ::: "memory")

// 28 chunks of 64 channels: [96 n][64 k] fp16 each (12 KB)
__device__ __align__(16) __half g_Wh[28 * 96 * 64];

__global__ void prep_W(const float* __restrict__ W0, const float* __restrict__ W1,
                       const float* __restrict__ W2)
{
    int idx = blockIdx.x * blockDim.x + threadIdx.x;
    if (idx >= 28 * 96 * 64) return;
    int ch = idx / 6144, rem = idx - ch * 6144;
    int n = rem >> 6, k = rem & 63;
    const float* W; int C, cb;
    if (ch < 4)       { W = W0; C = 256;  cb = ch * 64; }
    else if (ch < 12) { W = W1; C = 512;  cb = (ch - 4) * 64; }
    else              { W = W2; C = 1024; cb = (ch - 12) * 64; }
    float v = (n < 85) ? W[(size_t)n * C + cb + k] : 0.0f;
    g_Wh[idx] = __float2half(v);
}

__device__ __forceinline__ uint32_t h2u(__half2 h) {
    return *reinterpret_cast<uint32_t*>(&h);
}

template <int C, int NHW, int NX, int LEVEL>
__device__ __forceinline__
void run_level(const float* __restrict__ X, const float* __restrict__ bias,
               float* __restrict__ out, int lvlOff, int chBase, int b, int m0,
               char* sm, uint32_t sb)
{
    const int tid = threadIdx.x;
    const int lane = tid & 31, wid = tid >> 5;
    const int wm = wid >> 1, wn = wid & 1;
    constexpr int NCH = C / 64;
    const bool fullTile = (m0 + 128 <= NHW);
    const float* Xb = X + (size_t)b * C * NHW;

    // ---- hoisted addresses ----
    const int k0 = tid >> 5, m4 = tid & 31;
    const uint32_t offX0 = (uint32_t)(k0 * 256 + ((m4 * 8) ^ ((k0 & 7) << 4)));

    uint32_t aoffA[2];
    {
        const int mat = lane >> 3, r = lane & 7;
#pragma unroll
        for (int mf = 0; mf < 2; mf++) {
            int kb = ((mat >> 1) << 3) + r;
            int mb = (wm * 32 + mf * 16 + ((mat & 1) << 3)) * 2;
            aoffA[mf] = (uint32_t)(kb * 256 + (mb ^ (r << 4)));
        }
    }
    uint32_t relB[3];
    {
        const int grp = lane >> 3, rsel = lane & 7;
#pragma unroll
        for (int j = 0; j < 3; j++)
            relB[j] = (uint32_t)((wn * 48 + (j * 2 + (grp >> 1)) * 8 + rsel) * 144
                                 + (grp & 1) * 16);
    }

    // load half (32 k-rows) of a chunk into 4 float4 regs
    auto loadX = [&](int chk, int half, float4 (&vv)[4]) {
        const int rbase = chk * 64 + half * 32 + k0;
        if (fullTile) {
            const float* p = Xb + (size_t)rbase * NHW + m0 + m4 * 4;
#pragma unroll
            for (int it = 0; it < 4; it++)
                vv[it] = *reinterpret_cast<const float4*>(p + (size_t)(8 * it) * NHW);
        } else {
            int lim = NHW - 1 - m0;
#pragma unroll
            for (int it = 0; it < 4; it++) {
                const float* src = Xb + (size_t)(rbase + 8 * it) * NHW + m0;
                vv[it].x = src[min(m4 * 4 + 0, lim)];
                vv[it].y = src[min(m4 * 4 + 1, lim)];
                vv[it].z = src[min(m4 * 4 + 2, lim)];
                vv[it].w = src[min(m4 * 4 + 3, lim)];
            }
        }
    };

    auto convertX = [&](const float4 (&vv)[4], uint32_t xsOff, int half) {
        uint32_t base = xsOff + offX0 + (uint32_t)half * 8192;
#pragma unroll
        for (int it = 0; it < 4; it++) {
            __half2 h0 = __floats2half2_rn(vv[it].x, vv[it].y);
            __half2 h1 = __floats2half2_rn(vv[it].z, vv[it].w);
            *reinterpret_cast<uint2*>(sm + base + it * 2048) = make_uint2(h2u(h0), h2u(h1));
        }
    };

    // W: 96 rows x 128B = 768 x 16B units; thread does units tid, +256, +512
    auto stageW = [&](int chk, uint32_t wsOff) {
        const uint4* wsrc = reinterpret_cast<const uint4*>(
            &g_Wh[(size_t)(chBase + chk) * 6144]);
#pragma unroll
        for (int it = 0; it < 3; it++) {
            uint32_t uu = tid + it * TPB;
            CP_ASYNC16(sb + wsOff + (uu >> 3) * 144 + (uu & 7) * 16, wsrc + uu);
        }
        CP_COMMIT();
    };

    // ---- fp16 accumulators: 2 regs per (mf,f) tile ----
    uint32_t acc[2][6][2];
#pragma unroll
    for (int mf = 0; mf < 2; mf++)
#pragma unroll
        for (int f = 0; f < 6; f++) { acc[mf][f][0] = 0u; acc[mf][f][1] = 0u; }

    auto mmaStep = [&](uint32_t xbase, uint32_t wbase, int ks) {
        uint32_t af[2][4];
        LDMX4T(af[0], xbase + aoffA[0] + ks * 4096);
        LDMX4T(af[1], xbase + aoffA[1] + ks * 4096);
#pragma unroll
        for (int j = 0; j < 3; j++) {
            uint32_t br[4];
            LDMX4(br, wbase + relB[j] + ks * 32);
            MMA16816H(acc[0][2 * j + 0], af[0], br[0], br[1]);
            MMA16816H(acc[1][2 * j + 0], af[1], br[0], br[1]);
            MMA16816H(acc[0][2 * j + 1], af[0], br[2], br[3]);
            MMA16816H(acc[1][2 * j + 1], af[1], br[2], br[3]);
        }
    };

    // ---- overlapped prologue ----
    float4 v[4];
    {
        float4 u[4];
        loadX(0, 0, v);
        loadX(0, 1, u);
        stageW(0, WS0);
        convertX(v, XS0, 0);
        convertX(u, XS0, 1);
    }
    loadX(1 < NCH ? 1 : 0, 0, v);
    CP_WAIT0();
    __syncthreads();

    for (int chk = 0; chk < NCH; chk++) {
        const uint32_t xbase = sb + ((chk & 1) ? XS1 : XS0);
        const uint32_t wbase = sb + ((chk & 1) ? WS1 : WS0);
        const uint32_t xsNxt = (chk & 1) ? XS0 : XS1;
        const uint32_t wsNxt = (chk & 1) ? WS0 : WS1;
        const bool more = (chk + 1 < NCH);

        if (more) {
            stageW(chk + 1, wsNxt);
            convertX(v, xsNxt, 0);
            loadX(chk + 1, 1, v);
        }

        mmaStep(xbase, wbase, 0);
        mmaStep(xbase, wbase, 1);

        if (more) {
            convertX(v, xsNxt, 1);
            if (chk + 2 < NCH) loadX(chk + 2, 0, v);
        }

        mmaStep(xbase, wbase, 2);
        mmaStep(xbase, wbase, 3);

        CP_WAIT0();
        __syncthreads();
    }

    // ---- unpack to fp32, bias + sigmoid ----
    const int g = lane >> 2, c0 = lane & 3;
    float fa[2][6][4];
#pragma unroll
    for (int f = 0; f < 6; f++) {
        int nb = wn * 48 + f * 8 + c0 * 2;
        float bv0 = (nb < 85) ? __ldg(&bias[nb]) : 0.0f;
        float bv1 = (nb + 1 < 85) ? __ldg(&bias[nb + 1]) : 0.0f;
#pragma unroll
        for (int mf = 0; mf < 2; mf++)
#pragma unroll
            for (int h = 0; h < 2; h++) {
                float2 t = __half22float2(*reinterpret_cast<__half2*>(&acc[mf][f][h]));
                float p0 = t.x + bv0;
                float p1 = t.y + bv1;
                fa[mf][f][h * 2 + 0] = __fdividef(1.0f, 1.0f + __expf(-p0));
                fa[mf][f][h * 2 + 1] = __fdividef(1.0f, 1.0f + __expf(-p1));
            }
    }

    // ---- box decode (channels 0..3 live in wn==0, f==0, c0<2) ----
    if (wn == 0) {
        const float power = (float)(1 << LEVEL);
        const float strd  = (float)(8 << LEVEL);
#pragma unroll
        for (int mf = 0; mf < 2; mf++)
#pragma unroll
            for (int h = 0; h < 2; h++) {
                float s0 = fa[mf][0][h * 2 + 0];
                float s1 = fa[mf][0][h * 2 + 1];
                float q0 = 4.0f * s0 * s0 * power;
                float q1 = 4.0f * s1 * s1 * power;
                float p0 = __shfl_xor_sync(0xffffffffu, q0, 1);
                float p1 = __shfl_xor_sync(0xffffffffu, q1, 1);
                float dx1 = (c0 == 0) ? q0 : p0;
                float dy1 = (c0 == 0) ? q1 : p1;
                float dx2 = (c0 == 0) ? p0 : q0;
                float dy2 = (c0 == 0) ? p1 : q1;
                int pos = m0 + wm * 32 + mf * 16 + h * 8 + g;
                int iy = pos / NX, ix = pos - iy * NX;
                float x1 = ((float)ix + 1.0f - dx1) * strd;
                float y1 = ((float)iy + 1.0f - dy1) * strd;
                float x2 = ((float)ix + dx2) * strd;
                float y2 = ((float)iy + dy2) * strd;
                if (c0 == 0) {
                    fa[mf][0][h * 2 + 0] = 0.5f * (x1 + x2);
                    fa[mf][0][h * 2 + 1] = 0.5f * (y1 + y2);
                } else if (c0 == 1) {
                    fa[mf][0][h * 2 + 0] = x2 - x1;
                    fa[mf][0][h * 2 + 1] = y2 - y1;
                }
            }
    }

    // ---- staged coalesced store: 2 waves of 64 positions ----
    float* S = reinterpret_cast<float*>(sm);
#pragma unroll
    for (int w = 0; w < 2; w++) {
        __syncthreads();
        if ((wm >> 1) == w) {
            int mbase = (wm & 1) * 32;
#pragma unroll
            for (int mf = 0; mf < 2; mf++)
#pragma unroll
                for (int h = 0; h < 2; h++) {
                    int mrow = mbase + mf * 16 + h * 8 + g;
#pragma unroll
                    for (int f = 0; f < 6; f++) {
                        int n = wn * 48 + f * 8 + c0 * 2;
                        if (n + 1 < 85)
                            *reinterpret_cast<float2*>(&S[mrow * SROW + n]) =
                                make_float2(fa[mf][f][h * 2], fa[mf][f][h * 2 + 1]);
                        else if (n < 85)
                            S[mrow * SROW + n] = fa[mf][f][h * 2];
                    }
                }
        }
        __syncthreads();
        // division-free warp-per-row stores: warp wid handles rows wid+8r
        int valid = NHW - (m0 + w * 64);
        valid = valid < 0 ? 0 : (valid > 64 ? 64 : valid);
        float* ob = out + ((size_t)b * 8400 + lvlOff + m0 + w * 64) * 85;
#pragma unroll
        for (int r = 0; r < 8; r++) {
            int p = wid + r * 8;
            if (p < valid) {
                const float* srow = &S[p * SROW];
                float* orow = ob + (size_t)p * 85;
                orow[lane] = srow[lane];
                orow[lane + 32] = srow[lane + 32];
                if (lane < 21) orow[lane + 64] = srow[lane + 64];
            }
        }
    }
}

// grid order: L2 (longest, 16 chunks) first, then L1, then L0
__global__ __launch_bounds__(TPB, 3)
void detect_tc(const float* __restrict__ x0, const float* __restrict__ x1,
               const float* __restrict__ x2,
               const float* __restrict__ b0, const float* __restrict__ b1,
               const float* __restrict__ b2, float* __restrict__ out)
{
    extern __shared__ __align__(1024) char sm[];
    uint32_t sb = smem_u32(sm);
    int bid = blockIdx.x;
    if (bid < 64) {                      // L2: 4 tiles x 16 batch
        int b = bid >> 2, t = bid & 3;
        run_level<1024, 400, 20, 2>(x2, b2, out, 8000, 12, b, t * 128, sm, sb);
    } else if (bid < 272) {              // L1: 13 tiles x 16 batch
        int q = bid - 64;
        int b = q / 13, t = q - b * 13;
        run_level<512, 1600, 40, 1>(x1, b1, out, 6400, 4, b, t * 128, sm, sb);
    } else {                             // L0: 50 tiles x 16 batch
        int q = bid - 272;
        int b = q / 50, t = q - b * 50;
        run_level<256, 6400, 80, 0>(x0, b0, out, 0, 0, b, t * 128, sm, sb);
    }
}

extern "C" void kernel_launch(void* const* d_in, const int* in_sizes, int n_in,
                              void* d_out, int out_size)
{
    const float* x0 = (const float*)d_in[0];
    const float* x1 = (const float*)d_in[1];
    const float* x2 = (const float*)d_in[2];
    const float* W0 = (const float*)d_in[3];
    const float* b0 = (const float*)d_in[4];
    const float* W1 = (const float*)d_in[5];
    const float* b1 = (const float*)d_in[6];
    const float* W2 = (const float*)d_in[7];
    const float* b2 = (const float*)d_in[8];
    float* out = (float*)d_out;

    cudaFuncSetAttribute(detect_tc, cudaFuncAttributeMaxDynamicSharedMemorySize,
                         SMEM_BYTES);
    prep_W<<<(28 * 96 * 64 + 255) / 256, 256>>>(W0, W1, W2);
    detect_tc<<<64 + 208 + 800, TPB, SMEM_BYTES>>>(x0, x1, x2, b0, b1, b2, out);
}